// round 2
// baseline (speedup 1.0000x reference)
#include <cuda_runtime.h>

// ---------------------------------------------------------------------------
// SSIM (16,3,512,512) fp32, 11x11 Gaussian (sigma=1.5), zero pad, global mean.
// Separable conv. Horizontal 11-tap from SMEM staged padded row; vertical
// 11-tap via explicit shift ring A[0..10] (A[j] = partial for output m=ir-j).
// Distance-1 LDG prefetch, double-buffered SMEM, one __syncthreads per row.
// ---------------------------------------------------------------------------

#define TH      64                 // output rows per band
#define NROWS   (TH + 10)          // 74 input rows per band
#define IMW     512
#define IMH     512
#define NT      512                // one thread per column
#define NPLANES 48                 // 16 * 3
#define NBANDS  (IMH / TH)         // 8
#define NBLOCKS (NPLANES * NBANDS) // 384
#define SSIM_C1 0.0001f
#define SSIM_C2 0.0009f

__device__ float g_partials[NBLOCKS];

__global__ void __launch_bounds__(NT, 1)
ssim_main(const float* __restrict__ img1, const float* __restrict__ img2)
{
    // Normalized 1D Gaussian, sigma=1.5, 11 taps
    const float W[11] = {
        0.00102838f, 0.00759874f, 0.03600077f, 0.10936069f, 0.21300553f,
        0.26601180f,
        0.21300553f, 0.10936069f, 0.03600077f, 0.00759874f, 0.00102838f
    };

    const int band  = blockIdx.x;       // 0..7
    const int plane = blockIdx.y;       // 0..47
    const int t     = threadIdx.x;      // column 0..511
    const int r0    = band * TH;
    const int pbase = plane * (IMW * IMH);

    // Double-buffered padded rows: staged index j in [0,522) <-> image col j-5
    __shared__ float sx[2][522];
    __shared__ float sy[2][522];

    // Shift ring: A*[j] = partial vertical sum for output row m = ir - j
    float Ax[11], Ay[11], Axx[11], Ayy[11], Axy[11];
#pragma unroll
    for (int j = 0; j < 11; ++j) {
        Ax[j] = 0.f; Ay[j] = 0.f; Axx[j] = 0.f; Ayy[j] = 0.f; Axy[j] = 0.f;
    }

    // ---- row loader (guards implement zero padding) ----
    const int cmain = t - 5;            // staged slot t       <-> col t-5
    const bool mok  = (cmain >= 0);     // cmain <= 506 always
    const int ctail = 507 + t;          // staged slot 512+t   <-> col 507+t
    const bool tok  = (t < 5);          // only cols 507..511 are real

    float px0, px1, py0, py1;           // prefetch registers (single set)

    // prologue: load + stage row ir=0 into buffer 0
    {
        const int gr = r0 - 5;          // global row of ir=0
        px0 = px1 = py0 = py1 = 0.f;
        if ((unsigned)gr < (unsigned)IMH) {
            const int rb = pbase + gr * IMW;
            if (mok) { px0 = img1[rb + cmain]; py0 = img2[rb + cmain]; }
            if (tok) { px1 = img1[rb + ctail]; py1 = img2[rb + ctail]; }
        }
        sx[0][t] = px0;  sy[0][t] = py0;
        if (t < 10) { sx[0][512 + t] = px1; sy[0][512 + t] = py1; }
    }
    __syncthreads();

    float ssum = 0.f;

    for (int ir = 0; ir < NROWS; ++ir) {
        const int cb = ir & 1;          // buffer holding row ir
        const int nb = cb ^ 1;          // buffer for row ir+1

        // (1) prefetch row ir+1 (registers only; latency overlaps compute)
        const bool havenext = (ir + 1 < NROWS);
        if (havenext) {
            const int gr = r0 - 5 + (ir + 1);
            px0 = px1 = py0 = py1 = 0.f;
            if ((unsigned)gr < (unsigned)IMH) {
                const int rb = pbase + gr * IMW;
                if (mok) { px0 = img1[rb + cmain]; py0 = img2[rb + cmain]; }
                if (tok) { px1 = img1[rb + ctail]; py1 = img2[rb + ctail]; }
            }
        }

        // (2) horizontal 11-tap conv of 5 fields at column t from buffer cb
        const float* xr = sx[cb];
        const float* yr = sy[cb];
        float hx = 0.f, hy = 0.f, hxx = 0.f, hyy = 0.f, hxy = 0.f;
#pragma unroll
        for (int k = 0; k < 11; ++k) {
            const float xv = xr[t + k];
            const float yv = yr[t + k];
            hx  += W[k] * xv;
            hy  += W[k] * yv;
            hxx += W[k] * (xv * xv);
            hyy += W[k] * (yv * yv);
            hxy += W[k] * (xv * yv);
        }

        // (3) vertical ring update: output m = ir - j gets weight W[j]
#pragma unroll
        for (int j = 0; j < 11; ++j) {
            Ax[j]  += W[j] * hx;
            Ay[j]  += W[j] * hy;
            Axx[j] += W[j] * hxx;
            Ayy[j] += W[j] * hyy;
            Axy[j] += W[j] * hxy;
        }

        // (4) output row m = ir - 10 complete in slot 10
        if (ir >= 10) {
            const float mu1 = Ax[10], mu2 = Ay[10];
            const float m11 = mu1 * mu1;
            const float m22 = mu2 * mu2;
            const float m12 = mu1 * mu2;
            const float s1  = Axx[10] - m11;
            const float s2  = Ayy[10] - m22;
            const float s12 = Axy[10] - m12;
            const float num = (2.f * m12 + SSIM_C1) * (2.f * s12 + SSIM_C2);
            const float den = (m11 + m22 + SSIM_C1) * (s1 + s2 + SSIM_C2);
            ssum += num / den;
        }

        // (5) shift ring down (slot 10 retired, slot 0 freed for row ir+1)
#pragma unroll
        for (int j = 10; j >= 1; --j) {
            Ax[j]  = Ax[j - 1];
            Ay[j]  = Ay[j - 1];
            Axx[j] = Axx[j - 1];
            Ayy[j] = Ayy[j - 1];
            Axy[j] = Axy[j - 1];
        }
        Ax[0] = 0.f; Ay[0] = 0.f; Axx[0] = 0.f; Ayy[0] = 0.f; Axy[0] = 0.f;

        // (6) stage prefetched row ir+1 into buffer nb, one barrier per row
        if (havenext) {
            sx[nb][t] = px0;  sy[nb][t] = py0;
            if (t < 10) { sx[nb][512 + t] = px1; sy[nb][512 + t] = py1; }
        }
        __syncthreads();
    }

    // ---- deterministic block reduction ----
    const int lane = t & 31;
    const int wid  = t >> 5;
#pragma unroll
    for (int off = 16; off; off >>= 1)
        ssum += __shfl_xor_sync(0xffffffffu, ssum, off);

    __shared__ float wsum[16];
    if (lane == 0) wsum[wid] = ssum;
    __syncthreads();
    if (t == 0) {
        float v = 0.f;
#pragma unroll
        for (int i = 0; i < 16; ++i) v += wsum[i];
        g_partials[plane * NBANDS + band] = v;
    }
}

__global__ void ssim_reduce(float* __restrict__ out)
{
    __shared__ float s[128];
    float v = 0.f;
    for (int i = threadIdx.x; i < NBLOCKS; i += 128) v += g_partials[i];
    s[threadIdx.x] = v;
    __syncthreads();
#pragma unroll
    for (int st = 64; st; st >>= 1) {
        if (threadIdx.x < st) s[threadIdx.x] += s[threadIdx.x + st];
        __syncthreads();
    }
    if (threadIdx.x == 0)
        out[0] = s[0] * (1.0f / 12582912.0f);   // / (16*3*512*512)
}

extern "C" void kernel_launch(void* const* d_in, const int* in_sizes, int n_in,
                              void* d_out, int out_size)
{
    const float* img1 = (const float*)d_in[0];
    const float* img2 = (const float*)d_in[1];
    (void)in_sizes; (void)n_in; (void)out_size;

    dim3 grid(NBANDS, NPLANES);
    ssim_main<<<grid, NT>>>(img1, img2);
    ssim_reduce<<<1, 128>>>((float*)d_out);
}